// round 16
// baseline (speedup 1.0000x reference)
#include <cuda_runtime.h>
#include <cuda_fp16.h>
#include <math.h>
#include <stdint.h>

#define N       2048
#define ITERS   1000
#define TEMP    100.0f
#define EPS_CONV 1e-4f
#define EXT_T   12

#define SGRID   128
#define SBLOCK  512
#define WPC     16              // warps per CTA = rows per CTA (1 warp : 1 row)

// ---------------- scratch (static device globals; allocation-free) -------------
__device__ __half g_Eh [N * N];   // exp matrix, fp16
__device__ __half g_ETh[N * N];   // transpose, fp16
__device__ __half g_Gp[N * N];    // G' = v ⊙ rowSuffixSum(m), fp16
__device__ float g_u[N];
__device__ float g_v[N];
__device__ float g_rowmax[N];

__device__ unsigned g_count = 0;
__device__ unsigned g_gen   = 0;
__device__ unsigned g_delta[2] = {0, 0};

// ---------------- acquire/release grid barrier ---------------------------------
__device__ __forceinline__ void grid_sync() {
    __syncthreads();
    if (threadIdx.x == 0) {
        unsigned my;
        asm volatile("ld.acquire.gpu.global.u32 %0, [%1];" : "=r"(my) : "l"(&g_gen));
        unsigned old;
        asm volatile("atom.release.gpu.global.add.u32 %0, [%1], %2;"
                     : "=r"(old) : "l"(&g_count), "r"(1u));
        if (old == SGRID - 1) {
            asm volatile("st.relaxed.gpu.global.u32 [%0], %1;" :: "l"(&g_count), "r"(0u));
            asm volatile("st.release.gpu.global.u32 [%0], %1;" :: "l"(&g_gen), "r"(my + 1u));
        } else {
            unsigned cur;
            do {
                asm volatile("ld.acquire.gpu.global.u32 %0, [%1];" : "=r"(cur) : "l"(&g_gen));
            } while (cur == my);
        }
    }
    __syncthreads();
}

// ---------------- prep kernels ---------------------------------------------------
__global__ void rowmax_kernel(const float* __restrict__ A) {
    int row = blockIdx.x;
    const float* a = A + (size_t)row * N;
    float m = -3.0e38f;
    for (int j = threadIdx.x; j < N; j += blockDim.x) m = fmaxf(m, a[j]);
    __shared__ float s[256];
    s[threadIdx.x] = m;
    __syncthreads();
    for (int o = 128; o > 0; o >>= 1) {
        if (threadIdx.x < o) s[threadIdx.x] = fmaxf(s[threadIdx.x], s[threadIdx.x + o]);
        __syncthreads();
    }
    if (threadIdx.x == 0) {
        g_rowmax[row] = s[0];
        g_u[row] = 1.0f; g_v[row] = 1.0f;
        if (row < 2) g_delta[row] = 0u;
    }
}

__global__ void exp_kernel(const float* __restrict__ A) {
    __shared__ __half tile[32][33];
    int x = blockIdx.x * 32 + threadIdx.x;
    int y = blockIdx.y * 32 + threadIdx.y;
    float rm = g_rowmax[y];
    __half e = __float2half_rn(expf(TEMP * (A[(size_t)y * N + x] - rm)));
    g_Eh[(size_t)y * N + x] = e;
    tile[threadIdx.y][threadIdx.x] = e;
    __syncthreads();
    int tx = blockIdx.y * 32 + threadIdx.x;
    int ty = blockIdx.x * 32 + threadIdx.y;
    g_ETh[(size_t)ty * N + tx] = tile[threadIdx.x][threadIdx.y];
}

// ---------------- persistent Sinkhorn + extrapolation + fused G' ----------------
__device__ __forceinline__ float dot8(uint4 e, const float4* sv2i) {
    __half2 h0 = *(__half2*)&e.x, h1 = *(__half2*)&e.y,
            h2 = *(__half2*)&e.z, h3 = *(__half2*)&e.w;
    float2 f0 = __half22float2(h0), f1 = __half22float2(h1),
           f2 = __half22float2(h2), f3 = __half22float2(h3);
    float4 v0 = sv2i[0], v1 = sv2i[1];
    return f0.x*v0.x + f0.y*v0.y + f1.x*v0.z + f1.y*v0.w
         + f2.x*v1.x + f2.y*v1.y + f3.x*v1.z + f3.y*v1.w;
}

__device__ __forceinline__ uint32_t pack_h2(__half a, __half b) {
    __half2 t = __halves2half2(a, b);
    return *(uint32_t*)&t;
}

__global__ void __launch_bounds__(SBLOCK, 1) sinkhorn_kernel() {
    const int tid  = threadIdx.x;
    const int wid  = tid >> 5;
    const int lane = tid & 31;
    const int row  = blockIdx.x * WPC + wid;   // 128 * 16 = 2048 rows

    __shared__ float svec[N];
    __shared__ float sdel[WPC];
    __shared__ float sflag;
    float4* svec4 = (float4*)svec;

    const uint4* erow  = (const uint4*)g_Eh  + (size_t)row * (N / 8);
    const uint4* etrow = (const uint4*)g_ETh + (size_t)row * (N / 8);
    uint4 eR[8], etR[8];
#pragma unroll
    for (int i = 0; i < 8; ++i) {
        eR[i]  = erow [i * 32 + lane];
        etR[i] = etrow[i * 32 + lane];
    }

    float u_old = 1.0f, u_prev2 = 1.0f;

    for (int t = 0; t < ITERS; ++t) {
        // ---------- phase A: u = 1 / (E v) ----------
        {
            const float4* v4 = (const float4*)g_v;
            svec4[tid] = v4[tid];
            __syncthreads();

            float s = 0.0f;
#pragma unroll
            for (int i = 0; i < 8; ++i)
                s += dot8(eR[i], svec4 + 2 * (i * 32 + lane));
#pragma unroll
            for (int o = 16; o > 0; o >>= 1) s += __shfl_xor_sync(0xffffffffu, s, o);
            if (lane == 0) {
                float un = 1.0f / s;
                // one-shot geometric (Aitken) extrapolation of the dominant mode
                if (t == EXT_T) {
                    float d1 = un - u_old;
                    float d0 = u_old - u_prev2;
                    float r = (d0 != 0.0f) ? d1 / d0 : 0.0f;
                    r = fminf(fmaxf(r, 0.0f), 0.9f);
                    un += d1 * (r / (1.0f - r));
                }
                g_u[row] = un;
                sdel[wid] = fabsf(un - u_old) / u_old;
                u_prev2 = u_old;
                u_old = un;
            }
            __syncthreads();
            if (tid == 0) {
                float dm = 0.0f;
#pragma unroll
                for (int i = 0; i < WPC; ++i) dm = fmaxf(dm, sdel[i]);
                atomicMax(&g_delta[t & 1], __float_as_uint(dm));
            }
        }
        grid_sync();

        if (tid == 0) {
            unsigned db;
            asm volatile("ld.acquire.gpu.global.u32 %0, [%1];" : "=r"(db) : "l"(&g_delta[t & 1]));
            sflag = (t > 0 && __uint_as_float(db) < EPS_CONV) ? 1.0f : 0.0f;
            g_delta[(t + 1) & 1] = 0u;
        }

        // ---------- phase B: v = 1 / (ET u) ----------
        bool conv;
        {
            const float4* u4 = (const float4*)g_u;
            svec4[tid] = u4[tid];
            __syncthreads();
            conv = (sflag > 0.5f);

            float s = 0.0f;
#pragma unroll
            for (int i = 0; i < 8; ++i)
                s += dot8(etR[i], svec4 + 2 * (i * 32 + lane));
#pragma unroll
            for (int o = 16; o > 0; o >>= 1) s += __shfl_xor_sync(0xffffffffu, s, o);
            if (lane == 0) g_v[row] = 1.0f / s;
        }
        grid_sync();

        if (conv) break;
    }

    // ---------- fused epilogue: G'[row,k] = v_k * suffixSum_k(u_row * E[row,:] ⊙ v) ----------
    {
        const float4* v4 = (const float4*)g_v;
        svec4[tid] = v4[tid];
        __syncthreads();

        float uu = __shfl_sync(0xffffffffu, u_old, 0);

        float cs[8], ics[8], T[8];
#pragma unroll
        for (int i = 0; i < 8; ++i)
            cs[i] = uu * dot8(eR[i], svec4 + 2 * (i * 32 + lane));

#pragma unroll
        for (int i = 0; i < 8; ++i) {
            float x = cs[i];
#pragma unroll
            for (int o = 1; o < 32; o <<= 1) {
                float y = __shfl_up_sync(0xffffffffu, x, o);
                if (lane >= o) x += y;
            }
            ics[i] = x;
            T[i] = __shfl_sync(0xffffffffu, x, 31);
        }

        float offi[8], tot = 0.0f;
#pragma unroll
        for (int i = 0; i < 8; ++i) { offi[i] = tot; tot += T[i]; }

        uint4* gp = (uint4*)g_Gp + (size_t)row * (N / 8);
#pragma unroll
        for (int i = 0; i < 8; ++i) {
            float pf = offi[i] + ics[i] - cs[i];

            const float4* sv2 = svec4 + 2 * (i * 32 + lane);
            float4 v0 = sv2[0], v1 = sv2[1];
            float vv[8] = {v0.x, v0.y, v0.z, v0.w, v1.x, v1.y, v1.z, v1.w};

            uint4 e = eR[i];
            __half2 h0 = *(__half2*)&e.x, h1 = *(__half2*)&e.y,
                    h2 = *(__half2*)&e.z, h3 = *(__half2*)&e.w;
            float2 f0 = __half22float2(h0), f1 = __half22float2(h1),
                   f2 = __half22float2(h2), f3 = __half22float2(h3);
            float m[8];
            m[0] = uu * f0.x * vv[0];  m[1] = uu * f0.y * vv[1];
            m[2] = uu * f1.x * vv[2];  m[3] = uu * f1.y * vv[3];
            m[4] = uu * f2.x * vv[4];  m[5] = uu * f2.y * vv[5];
            m[6] = uu * f3.x * vv[6];  m[7] = uu * f3.y * vv[7];

            __half gh[8];
#pragma unroll
            for (int q = 0; q < 8; ++q) {
                float g = tot - pf;
                pf += m[q];
                gh[q] = __float2half_rn(g * vv[q]);
            }
            gp[i * 32 + lane] =
                make_uint4(pack_h2(gh[0],gh[1]), pack_h2(gh[2],gh[3]),
                           pack_h2(gh[4],gh[5]), pack_h2(gh[6],gh[7]));
        }
    }
}

// ================= mma.sync fp16-ACC GEMM: C[a,b] = u_a * dot(E[a,:], G'[b,:]) ===
// 512 threads (16 warps, 4x4), warp tile 32x32, BK=64, 3-stage pipeline.
// Inner chunk accumulates in fp16 (2x HMMA rate if pipe supports), promoted to
// fp32 every chunk (4 MMAs per acc between promotions -> ~1e-4 added error).
#define BK       64
#define KCHUNKS  (N / BK)              // 32
#define PITCH    72                    // halves per smem row (64 + 8 pad) -> 144B
#define TILE_B   (128 * PITCH * 2)     // 18432 bytes per tile
#define STAGE_B  (2 * TILE_B)          // A(E), B(G') = 36864 bytes
#define NSTAGE   3
#define GT       512

__device__ __forceinline__ uint32_t smem_u32(const void* p) {
    uint32_t a;
    asm("{ .reg .u64 t; cvta.to.shared.u64 t, %1; cvt.u32.u64 %0, t; }" : "=r"(a) : "l"(p));
    return a;
}
__device__ __forceinline__ void cp16(uint32_t dst, const void* src) {
    asm volatile("cp.async.cg.shared.global [%0], [%1], 16;" :: "r"(dst), "l"(src));
}
__device__ __forceinline__ void cp_commit() { asm volatile("cp.async.commit_group;" ::: "memory"); }
__device__ __forceinline__ void cp_wait1()  { asm volatile("cp.async.wait_group 1;" ::: "memory"); }

__device__ __forceinline__ void ldsm4(uint32_t addr, uint32_t* r) {
    asm volatile("ldmatrix.sync.aligned.m8n8.x4.shared.b16 {%0,%1,%2,%3}, [%4];"
                 : "=r"(r[0]), "=r"(r[1]), "=r"(r[2]), "=r"(r[3]) : "r"(addr));
}
// fp16-accumulator MMA: C fragments are two .b32 regs holding (c0,c1) and (c2,c3)
__device__ __forceinline__ void mma16816h(uint32_t* c, const uint32_t* a, uint32_t b0, uint32_t b1) {
    asm volatile("mma.sync.aligned.m16n8k16.row.col.f16.f16.f16.f16 "
                 "{%0,%1}, {%2,%3,%4,%5}, {%6,%7}, {%0,%1};"
                 : "+r"(c[0]), "+r"(c[1])
                 : "r"(a[0]), "r"(a[1]), "r"(a[2]), "r"(a[3]), "r"(b0), "r"(b1));
}

// load one stage: A rows [bi,bi+128), B rows [bj,bj+128), k window [k0,k0+64)
__device__ __forceinline__ void load_stage(uint32_t S, int bi, int bj, int k0, int tid) {
    const __half* gs0 = g_Eh + (size_t)bi * N + k0;
    const __half* gs1 = g_Gp + (size_t)bj * N + k0;
#pragma unroll
    for (int i = 0; i < 4; ++i) {
        int p = tid + i * GT;              // 0..2047
        int tile = p >> 10;                // 0..1
        int r = (p >> 3) & 127;
        int s = p & 7;
        const __half* src = (tile == 0 ? gs0 : gs1) + (size_t)r * N + s * 8;
        uint32_t dst = S + tile * TILE_B + r * (PITCH * 2) + s * 16;
        cp16(dst, src);
    }
}

__global__ void __launch_bounds__(GT, 1) gemm_kernel(float* __restrict__ C) {
    extern __shared__ char smem[];
    const uint32_t SB = smem_u32(smem);

    const int tid  = threadIdx.x;
    const int lane = tid & 31;
    const int wid  = tid >> 5;
    const int wm   = wid & 3;          // warp M index (0..3)
    const int wn   = wid >> 2;         // warp N index (0..3)
    const int bi   = blockIdx.y * 128;
    const int bj   = blockIdx.x * 128;

    const int arow = lane & 15;
    const int asel = lane >> 4;
    const int brow = (lane & 7) + ((lane >> 4) << 3);
    const int bsel = (lane >> 3) & 1;

    uint32_t aBase[2], bBase[2];
#pragma unroll
    for (int mi = 0; mi < 2; ++mi)
        aBase[mi] = (uint32_t)((wm * 32 + mi * 16 + arow) * (PITCH * 2) + (asel * 8) * 2);
#pragma unroll
    for (int np = 0; np < 2; ++np)
        bBase[np] = (uint32_t)((wn * 32 + np * 16 + brow) * (PITCH * 2) + (bsel * 8) * 2) + TILE_B;

    float acc[2][4][4];
#pragma unroll
    for (int mi = 0; mi < 2; ++mi)
#pragma unroll
        for (int ni = 0; ni < 4; ++ni)
#pragma unroll
            for (int q = 0; q < 4; ++q) acc[mi][ni][q] = 0.0f;

#pragma unroll
    for (int s = 0; s < NSTAGE - 1; ++s) {
        load_stage(SB + s * STAGE_B, bi, bj, s * BK, tid);
        cp_commit();
    }

    for (int c = 0; c < KCHUNKS; ++c) {
        cp_wait1();
        __syncthreads();

        if (c + NSTAGE - 1 < KCHUNKS)
            load_stage(SB + ((c + NSTAGE - 1) % NSTAGE) * STAGE_B, bi, bj, (c + NSTAGE - 1) * BK, tid);
        cp_commit();

        const uint32_t S = SB + (c % NSTAGE) * STAGE_B;

        // fp16 chunk accumulators (zeroed each chunk; 4 MMAs per acc)
        uint32_t accH[2][4][2];
#pragma unroll
        for (int mi = 0; mi < 2; ++mi)
#pragma unroll
            for (int ni = 0; ni < 4; ++ni) { accH[mi][ni][0] = 0u; accH[mi][ni][1] = 0u; }

#pragma unroll
        for (int ks = 0; ks < 4; ++ks) {
            const uint32_t kOff = ks * 32;   // 16 halves per k-slice
            uint32_t aF[2][4];
#pragma unroll
            for (int mi = 0; mi < 2; ++mi)
                ldsm4(S + aBase[mi] + kOff, aF[mi]);

            uint32_t bF[2][4];
#pragma unroll
            for (int np = 0; np < 2; ++np)
                ldsm4(S + bBase[np] + kOff, bF[np]);

#pragma unroll
            for (int np = 0; np < 2; ++np)
#pragma unroll
                for (int mi = 0; mi < 2; ++mi) {
                    mma16816h(accH[mi][2 * np],     aF[mi], bF[np][0], bF[np][1]);
                    mma16816h(accH[mi][2 * np + 1], aF[mi], bF[np][2], bF[np][3]);
                }
        }

        // promote chunk partials to fp32
#pragma unroll
        for (int mi = 0; mi < 2; ++mi)
#pragma unroll
            for (int ni = 0; ni < 4; ++ni) {
                float2 p0 = __half22float2(*(__half2*)&accH[mi][ni][0]);
                float2 p1 = __half22float2(*(__half2*)&accH[mi][ni][1]);
                acc[mi][ni][0] += p0.x; acc[mi][ni][1] += p0.y;
                acc[mi][ni][2] += p1.x; acc[mi][ni][3] += p1.y;
            }
    }

    // epilogue: scale by u_a and store (warp tile 32x32)
    const int gid = lane >> 2;
    const int tig = lane & 3;
#pragma unroll
    for (int mi = 0; mi < 2; ++mi) {
        int a0 = bi + wm * 32 + mi * 16 + gid;
        float u0 = g_u[a0];
        float u8 = g_u[a0 + 8];
#pragma unroll
        for (int ni = 0; ni < 4; ++ni) {
            int b0 = bj + wn * 32 + ni * 8 + tig * 2;
            *(float2*)(C + (size_t)a0 * N + b0) =
                make_float2(acc[mi][ni][0] * u0, acc[mi][ni][1] * u0);
            *(float2*)(C + (size_t)(a0 + 8) * N + b0) =
                make_float2(acc[mi][ni][2] * u8, acc[mi][ni][3] * u8);
        }
    }
}

// ---------------- launch --------------------------------------------------------
extern "C" void kernel_launch(void* const* d_in, const int* in_sizes, int n_in,
                              void* d_out, int out_size) {
    const float* A = (const float*)d_in[0];
    float* out = (float*)d_out;

    static const int GEMM_SMEM = NSTAGE * STAGE_B;   // 110592 bytes
    cudaFuncSetAttribute(gemm_kernel, cudaFuncAttributeMaxDynamicSharedMemorySize, GEMM_SMEM);

    rowmax_kernel<<<N, 256>>>(A);
    exp_kernel<<<dim3(N / 32, N / 32), dim3(32, 32)>>>(A);
    sinkhorn_kernel<<<SGRID, SBLOCK>>>();
    gemm_kernel<<<dim3(N / 128, N / 128), GT, GEMM_SMEM>>>(out);
}

// round 17
// speedup vs baseline: 1.1806x; 1.1806x over previous
#include <cuda_runtime.h>
#include <cuda_fp16.h>
#include <math.h>
#include <stdint.h>

#define N       2048
#define ITERS   1000
#define TEMP    100.0f
#define EPS_CONV 1e-4f
#define EXT_T   12

#define SGRID   128
#define SBLOCK  512
#define WPC     16              // warps per CTA = rows per CTA (1 warp : 1 row)

// ---------------- scratch (static device globals; allocation-free) -------------
__device__ __half g_Eh [N * N];   // exp matrix, fp16
__device__ __half g_ETh[N * N];   // transpose, fp16
__device__ __half g_Gp[N * N];    // G' = v ⊙ rowSuffixSum(m), fp16
__device__ float g_u[N];
__device__ float g_v[N];
__device__ float g_rowmax[N];

__device__ unsigned g_count = 0;
__device__ unsigned g_gen   = 0;
__device__ unsigned g_delta[2] = {0, 0};

// ---------------- acquire/release grid barrier ---------------------------------
__device__ __forceinline__ void grid_sync() {
    __syncthreads();
    if (threadIdx.x == 0) {
        unsigned my;
        asm volatile("ld.acquire.gpu.global.u32 %0, [%1];" : "=r"(my) : "l"(&g_gen));
        unsigned old;
        asm volatile("atom.release.gpu.global.add.u32 %0, [%1], %2;"
                     : "=r"(old) : "l"(&g_count), "r"(1u));
        if (old == SGRID - 1) {
            asm volatile("st.relaxed.gpu.global.u32 [%0], %1;" :: "l"(&g_count), "r"(0u));
            asm volatile("st.release.gpu.global.u32 [%0], %1;" :: "l"(&g_gen), "r"(my + 1u));
        } else {
            unsigned cur;
            do {
                asm volatile("ld.acquire.gpu.global.u32 %0, [%1];" : "=r"(cur) : "l"(&g_gen));
            } while (cur == my);
        }
    }
    __syncthreads();
}

// ---------------- prep kernels ---------------------------------------------------
__global__ void rowmax_kernel(const float* __restrict__ A) {
    int row = blockIdx.x;
    const float* a = A + (size_t)row * N;
    float m = -3.0e38f;
    for (int j = threadIdx.x; j < N; j += blockDim.x) m = fmaxf(m, a[j]);
    __shared__ float s[256];
    s[threadIdx.x] = m;
    __syncthreads();
    for (int o = 128; o > 0; o >>= 1) {
        if (threadIdx.x < o) s[threadIdx.x] = fmaxf(s[threadIdx.x], s[threadIdx.x + o]);
        __syncthreads();
    }
    if (threadIdx.x == 0) {
        g_rowmax[row] = s[0];
        g_u[row] = 1.0f; g_v[row] = 1.0f;
        if (row < 2) g_delta[row] = 0u;
    }
}

__global__ void exp_kernel(const float* __restrict__ A) {
    __shared__ __half tile[32][33];
    int x = blockIdx.x * 32 + threadIdx.x;
    int y = blockIdx.y * 32 + threadIdx.y;
    float rm = g_rowmax[y];
    __half e = __float2half_rn(expf(TEMP * (A[(size_t)y * N + x] - rm)));
    g_Eh[(size_t)y * N + x] = e;
    tile[threadIdx.y][threadIdx.x] = e;
    __syncthreads();
    int tx = blockIdx.y * 32 + threadIdx.x;
    int ty = blockIdx.x * 32 + threadIdx.y;
    g_ETh[(size_t)ty * N + tx] = tile[threadIdx.x][threadIdx.y];
}

// ---------------- persistent Sinkhorn + extrapolation + fused G' ----------------
__device__ __forceinline__ float dot8(uint4 e, const float4* sv2i) {
    __half2 h0 = *(__half2*)&e.x, h1 = *(__half2*)&e.y,
            h2 = *(__half2*)&e.z, h3 = *(__half2*)&e.w;
    float2 f0 = __half22float2(h0), f1 = __half22float2(h1),
           f2 = __half22float2(h2), f3 = __half22float2(h3);
    float4 v0 = sv2i[0], v1 = sv2i[1];
    return f0.x*v0.x + f0.y*v0.y + f1.x*v0.z + f1.y*v0.w
         + f2.x*v1.x + f2.y*v1.y + f3.x*v1.z + f3.y*v1.w;
}

__device__ __forceinline__ uint32_t pack_h2(__half a, __half b) {
    __half2 t = __halves2half2(a, b);
    return *(uint32_t*)&t;
}

__global__ void __launch_bounds__(SBLOCK, 1) sinkhorn_kernel() {
    const int tid  = threadIdx.x;
    const int wid  = tid >> 5;
    const int lane = tid & 31;
    const int row  = blockIdx.x * WPC + wid;   // 128 * 16 = 2048 rows

    __shared__ float svec[N];
    __shared__ float sdel[WPC];
    __shared__ float sflag;
    float4* svec4 = (float4*)svec;

    const uint4* erow  = (const uint4*)g_Eh  + (size_t)row * (N / 8);
    const uint4* etrow = (const uint4*)g_ETh + (size_t)row * (N / 8);
    uint4 eR[8], etR[8];
#pragma unroll
    for (int i = 0; i < 8; ++i) {
        eR[i]  = erow [i * 32 + lane];
        etR[i] = etrow[i * 32 + lane];
    }

    float u_old = 1.0f, u_prev2 = 1.0f;

    for (int t = 0; t < ITERS; ++t) {
        // ---------- phase A: u = 1 / (E v) ----------
        {
            const float4* v4 = (const float4*)g_v;
            svec4[tid] = v4[tid];
            __syncthreads();

            float s = 0.0f;
#pragma unroll
            for (int i = 0; i < 8; ++i)
                s += dot8(eR[i], svec4 + 2 * (i * 32 + lane));
#pragma unroll
            for (int o = 16; o > 0; o >>= 1) s += __shfl_xor_sync(0xffffffffu, s, o);
            if (lane == 0) {
                float un = 1.0f / s;
                // one-shot geometric (Aitken) extrapolation of the dominant mode
                if (t == EXT_T) {
                    float d1 = un - u_old;
                    float d0 = u_old - u_prev2;
                    float r = (d0 != 0.0f) ? d1 / d0 : 0.0f;
                    r = fminf(fmaxf(r, 0.0f), 0.9f);
                    un += d1 * (r / (1.0f - r));
                }
                g_u[row] = un;
                sdel[wid] = fabsf(un - u_old) / u_old;
                u_prev2 = u_old;
                u_old = un;
            }
            __syncthreads();
            if (tid == 0) {
                float dm = 0.0f;
#pragma unroll
                for (int i = 0; i < WPC; ++i) dm = fmaxf(dm, sdel[i]);
                atomicMax(&g_delta[t & 1], __float_as_uint(dm));
            }
        }
        grid_sync();

        if (tid == 0) {
            unsigned db;
            asm volatile("ld.acquire.gpu.global.u32 %0, [%1];" : "=r"(db) : "l"(&g_delta[t & 1]));
            sflag = (t > 0 && __uint_as_float(db) < EPS_CONV) ? 1.0f : 0.0f;
            g_delta[(t + 1) & 1] = 0u;
        }

        // ---------- phase B: v = 1 / (ET u) ----------
        bool conv;
        {
            const float4* u4 = (const float4*)g_u;
            svec4[tid] = u4[tid];
            __syncthreads();
            conv = (sflag > 0.5f);

            float s = 0.0f;
#pragma unroll
            for (int i = 0; i < 8; ++i)
                s += dot8(etR[i], svec4 + 2 * (i * 32 + lane));
#pragma unroll
            for (int o = 16; o > 0; o >>= 1) s += __shfl_xor_sync(0xffffffffu, s, o);
            if (lane == 0) g_v[row] = 1.0f / s;
        }
        grid_sync();

        if (conv) break;
    }

    // ---------- fused epilogue: G'[row,k] = v_k * suffixSum_k(u_row * E[row,:] ⊙ v) ----------
    {
        const float4* v4 = (const float4*)g_v;
        svec4[tid] = v4[tid];
        __syncthreads();

        float uu = __shfl_sync(0xffffffffu, u_old, 0);

        float cs[8], ics[8], T[8];
#pragma unroll
        for (int i = 0; i < 8; ++i)
            cs[i] = uu * dot8(eR[i], svec4 + 2 * (i * 32 + lane));

#pragma unroll
        for (int i = 0; i < 8; ++i) {
            float x = cs[i];
#pragma unroll
            for (int o = 1; o < 32; o <<= 1) {
                float y = __shfl_up_sync(0xffffffffu, x, o);
                if (lane >= o) x += y;
            }
            ics[i] = x;
            T[i] = __shfl_sync(0xffffffffu, x, 31);
        }

        float offi[8], tot = 0.0f;
#pragma unroll
        for (int i = 0; i < 8; ++i) { offi[i] = tot; tot += T[i]; }

        uint4* gp = (uint4*)g_Gp + (size_t)row * (N / 8);
#pragma unroll
        for (int i = 0; i < 8; ++i) {
            float pf = offi[i] + ics[i] - cs[i];

            const float4* sv2 = svec4 + 2 * (i * 32 + lane);
            float4 v0 = sv2[0], v1 = sv2[1];
            float vv[8] = {v0.x, v0.y, v0.z, v0.w, v1.x, v1.y, v1.z, v1.w};

            uint4 e = eR[i];
            __half2 h0 = *(__half2*)&e.x, h1 = *(__half2*)&e.y,
                    h2 = *(__half2*)&e.z, h3 = *(__half2*)&e.w;
            float2 f0 = __half22float2(h0), f1 = __half22float2(h1),
                   f2 = __half22float2(h2), f3 = __half22float2(h3);
            float m[8];
            m[0] = uu * f0.x * vv[0];  m[1] = uu * f0.y * vv[1];
            m[2] = uu * f1.x * vv[2];  m[3] = uu * f1.y * vv[3];
            m[4] = uu * f2.x * vv[4];  m[5] = uu * f2.y * vv[5];
            m[6] = uu * f3.x * vv[6];  m[7] = uu * f3.y * vv[7];

            __half gh[8];
#pragma unroll
            for (int q = 0; q < 8; ++q) {
                float g = tot - pf;
                pf += m[q];
                gh[q] = __float2half_rn(g * vv[q]);
            }
            gp[i * 32 + lane] =
                make_uint4(pack_h2(gh[0],gh[1]), pack_h2(gh[2],gh[3]),
                           pack_h2(gh[4],gh[5]), pack_h2(gh[6],gh[7]));
        }
    }
}

// ================= mma.sync fp32-acc GEMM: C[a,b] = u_a * dot(E[a,:], G'[b,:]) ===
// 512 threads (16 warps, 4x4), warp tile 32x32, BK=64, 3-stage pipeline, occ 2.
// (R15 configuration — fp32-acc HMMA is the measured throughput floor.)
#define BK       64
#define KCHUNKS  (N / BK)              // 32
#define PITCH    72                    // halves per smem row (64 + 8 pad) -> 144B
#define TILE_B   (128 * PITCH * 2)     // 18432 bytes per tile
#define STAGE_B  (2 * TILE_B)          // A(E), B(G') = 36864 bytes
#define NSTAGE   3
#define GT       512

__device__ __forceinline__ uint32_t smem_u32(const void* p) {
    uint32_t a;
    asm("{ .reg .u64 t; cvta.to.shared.u64 t, %1; cvt.u32.u64 %0, t; }" : "=r"(a) : "l"(p));
    return a;
}
__device__ __forceinline__ void cp16(uint32_t dst, const void* src) {
    asm volatile("cp.async.cg.shared.global [%0], [%1], 16;" :: "r"(dst), "l"(src));
}
__device__ __forceinline__ void cp_commit() { asm volatile("cp.async.commit_group;" ::: "memory"); }
__device__ __forceinline__ void cp_wait1()  { asm volatile("cp.async.wait_group 1;" ::: "memory"); }

__device__ __forceinline__ void ldsm4(uint32_t addr, uint32_t* r) {
    asm volatile("ldmatrix.sync.aligned.m8n8.x4.shared.b16 {%0,%1,%2,%3}, [%4];"
                 : "=r"(r[0]), "=r"(r[1]), "=r"(r[2]), "=r"(r[3]) : "r"(addr));
}
__device__ __forceinline__ void mma16816(float* c, const uint32_t* a, uint32_t b0, uint32_t b1) {
    asm volatile("mma.sync.aligned.m16n8k16.row.col.f32.f16.f16.f32 "
                 "{%0,%1,%2,%3}, {%4,%5,%6,%7}, {%8,%9}, {%0,%1,%2,%3};"
                 : "+f"(c[0]), "+f"(c[1]), "+f"(c[2]), "+f"(c[3])
                 : "r"(a[0]), "r"(a[1]), "r"(a[2]), "r"(a[3]), "r"(b0), "r"(b1));
}

// load one stage: A rows [bi,bi+128), B rows [bj,bj+128), k window [k0,k0+64)
__device__ __forceinline__ void load_stage(uint32_t S, int bi, int bj, int k0, int tid) {
    const __half* gs0 = g_Eh + (size_t)bi * N + k0;
    const __half* gs1 = g_Gp + (size_t)bj * N + k0;
#pragma unroll
    for (int i = 0; i < 4; ++i) {
        int p = tid + i * GT;              // 0..2047
        int tile = p >> 10;                // 0..1
        int r = (p >> 3) & 127;
        int s = p & 7;
        const __half* src = (tile == 0 ? gs0 : gs1) + (size_t)r * N + s * 8;
        uint32_t dst = S + tile * TILE_B + r * (PITCH * 2) + s * 16;
        cp16(dst, src);
    }
}

__global__ void __launch_bounds__(GT, 2) gemm_kernel(float* __restrict__ C) {
    extern __shared__ char smem[];
    const uint32_t SB = smem_u32(smem);

    const int tid  = threadIdx.x;
    const int lane = tid & 31;
    const int wid  = tid >> 5;
    const int wm   = wid & 3;          // warp M index (0..3)
    const int wn   = wid >> 2;         // warp N index (0..3)
    const int bi   = blockIdx.y * 128;
    const int bj   = blockIdx.x * 128;

    const int arow = lane & 15;
    const int asel = lane >> 4;
    const int brow = (lane & 7) + ((lane >> 4) << 3);
    const int bsel = (lane >> 3) & 1;

    uint32_t aBase[2], bBase[2];
#pragma unroll
    for (int mi = 0; mi < 2; ++mi)
        aBase[mi] = (uint32_t)((wm * 32 + mi * 16 + arow) * (PITCH * 2) + (asel * 8) * 2);
#pragma unroll
    for (int np = 0; np < 2; ++np)
        bBase[np] = (uint32_t)((wn * 32 + np * 16 + brow) * (PITCH * 2) + (bsel * 8) * 2) + TILE_B;

    float acc[2][4][4];
#pragma unroll
    for (int mi = 0; mi < 2; ++mi)
#pragma unroll
        for (int ni = 0; ni < 4; ++ni)
#pragma unroll
            for (int q = 0; q < 4; ++q) acc[mi][ni][q] = 0.0f;

#pragma unroll
    for (int s = 0; s < NSTAGE - 1; ++s) {
        load_stage(SB + s * STAGE_B, bi, bj, s * BK, tid);
        cp_commit();
    }

    for (int c = 0; c < KCHUNKS; ++c) {
        cp_wait1();
        __syncthreads();

        if (c + NSTAGE - 1 < KCHUNKS)
            load_stage(SB + ((c + NSTAGE - 1) % NSTAGE) * STAGE_B, bi, bj, (c + NSTAGE - 1) * BK, tid);
        cp_commit();

        const uint32_t S = SB + (c % NSTAGE) * STAGE_B;

#pragma unroll
        for (int ks = 0; ks < 4; ++ks) {
            const uint32_t kOff = ks * 32;   // 16 halves per k-slice
            uint32_t aF[2][4];
#pragma unroll
            for (int mi = 0; mi < 2; ++mi)
                ldsm4(S + aBase[mi] + kOff, aF[mi]);

            uint32_t bF[2][4];
#pragma unroll
            for (int np = 0; np < 2; ++np)
                ldsm4(S + bBase[np] + kOff, bF[np]);

            // 8 MMAs, all-independent accumulators
#pragma unroll
            for (int np = 0; np < 2; ++np)
#pragma unroll
                for (int mi = 0; mi < 2; ++mi) {
                    mma16816(acc[mi][2 * np],     aF[mi], bF[np][0], bF[np][1]);
                    mma16816(acc[mi][2 * np + 1], aF[mi], bF[np][2], bF[np][3]);
                }
        }
    }

    // epilogue: scale by u_a and store (warp tile 32x32)
    const int gid = lane >> 2;
    const int tig = lane & 3;
#pragma unroll
    for (int mi = 0; mi < 2; ++mi) {
        int a0 = bi + wm * 32 + mi * 16 + gid;
        float u0 = g_u[a0];
        float u8 = g_u[a0 + 8];
#pragma unroll
        for (int ni = 0; ni < 4; ++ni) {
            int b0 = bj + wn * 32 + ni * 8 + tig * 2;
            *(float2*)(C + (size_t)a0 * N + b0) =
                make_float2(acc[mi][ni][0] * u0, acc[mi][ni][1] * u0);
            *(float2*)(C + (size_t)(a0 + 8) * N + b0) =
                make_float2(acc[mi][ni][2] * u8, acc[mi][ni][3] * u8);
        }
    }
}

// ---------------- launch --------------------------------------------------------
extern "C" void kernel_launch(void* const* d_in, const int* in_sizes, int n_in,
                              void* d_out, int out_size) {
    const float* A = (const float*)d_in[0];
    float* out = (float*)d_out;

    static const int GEMM_SMEM = NSTAGE * STAGE_B;   // 110592 bytes
    cudaFuncSetAttribute(gemm_kernel, cudaFuncAttributeMaxDynamicSharedMemorySize, GEMM_SMEM);

    rowmax_kernel<<<N, 256>>>(A);
    exp_kernel<<<dim3(N / 32, N / 32), dim3(32, 32)>>>(A);
    sinkhorn_kernel<<<SGRID, SBLOCK>>>();
    gemm_kernel<<<dim3(N / 128, N / 128), GT, GEMM_SMEM>>>(out);
}